// round 9
// baseline (speedup 1.0000x reference)
#include <cuda_runtime.h>
#include <cuda_fp16.h>
#include <cstdint>

#define H 128
#define NMAX 524288

// Scratch: segment sums, per-graph constant c, fp16 copy of node features.
__device__ float g_agg[4096 * 128];
__device__ float g_c[4096 * 128];
__device__ __align__(16) uint2 g_n16[(size_t)NMAX * 32];   // [N][128] fp16

// ============================================================================
// Base-target PTX helpers
// ============================================================================
__device__ __forceinline__ uint32_t pack_f16x2(float lo, float hi) {
    uint32_t u;
    asm("cvt.rn.f16x2.f32 %0, %1, %2;" : "=r"(u) : "f"(hi), "f"(lo));
    return u;
}
__device__ __forceinline__ uint32_t smem_u32_of(const void* p) {
    uint32_t a;
    asm("{ .reg .u64 t; cvta.to.shared.u64 t, %1; cvt.u32.u64 %0, t; }"
        : "=r"(a) : "l"(p));
    return a;
}
__device__ __forceinline__ void mma16(float* d, const uint32_t* a,
                                      uint32_t b0, uint32_t b1) {
    asm volatile(
        "mma.sync.aligned.m16n8k16.row.col.f32.f16.f16.f32 "
        "{%0,%1,%2,%3},{%4,%5,%6,%7},{%8,%9},{%0,%1,%2,%3};"
        : "+f"(d[0]), "+f"(d[1]), "+f"(d[2]), "+f"(d[3])
        : "r"(a[0]), "r"(a[1]), "r"(a[2]), "r"(a[3]), "r"(b0), "r"(b1));
}
__device__ __forceinline__ void ldsm4(uint32_t& r0, uint32_t& r1,
                                      uint32_t& r2, uint32_t& r3, uint32_t addr) {
    asm volatile("ldmatrix.sync.aligned.m8n8.x4.shared.b16 {%0,%1,%2,%3}, [%4];"
                 : "=r"(r0), "=r"(r1), "=r"(r2), "=r"(r3) : "r"(addr));
}
#define CP_ASYNC16(dst, src) \
    asm volatile("cp.async.cg.shared.global [%0], [%1], 16;" :: "r"(dst), "l"(src))
#define CP_COMMIT() asm volatile("cp.async.commit_group;" ::: "memory")
#define CP_WAIT(n)  asm volatile("cp.async.wait_group %0;" :: "n"(n) : "memory")

// ============================================================================
// Small kernels
// ============================================================================
__global__ void zero_agg_kernel(int n) {
    int i = blockIdx.x * blockDim.x + threadIdx.x;
    if (i < n) g_agg[i] = 0.0f;
}

// seg_sum + fp16 convert: 512 rows/block, 256 threads, float4 lanes.
__global__ void seg_sum_cvt_kernel(const float4* __restrict__ node4,
                                   const int* __restrict__ seg) {
    __shared__ int sseg[512];
    const int base = blockIdx.x * 512;
    const int tid = threadIdx.x;
    for (int i = tid; i < 512; i += 256) sseg[i] = seg[base + i];
    __syncthreads();
    const int c4 = tid & 31, rp = tid >> 5;
    const int r0 = rp * 64;
    float4 acc = make_float4(0.f, 0.f, 0.f, 0.f);
    int cur = sseg[r0];
    #pragma unroll 4
    for (int i = 0; i < 64; ++i) {
        const int r = r0 + i;
        const int id = sseg[r];
        if (id != cur) {
            float* dst = &g_agg[cur * H + c4 * 4];
            atomicAdd(dst + 0, acc.x); atomicAdd(dst + 1, acc.y);
            atomicAdd(dst + 2, acc.z); atomicAdd(dst + 3, acc.w);
            acc = make_float4(0.f, 0.f, 0.f, 0.f);
            cur = id;
        }
        float4 v = node4[(size_t)(base + r) * 32 + c4];
        uint2 hv;
        hv.x = pack_f16x2(v.x, v.y);
        hv.y = pack_f16x2(v.z, v.w);
        g_n16[(size_t)(base + r) * 32 + c4] = hv;
        acc.x += v.x; acc.y += v.y; acc.z += v.z; acc.w += v.w;
    }
    float* dst = &g_agg[cur * H + c4 * 4];
    atomicAdd(dst + 0, acc.x); atomicAdd(dst + 1, acc.y);
    atomicAdd(dst + 2, acc.z); atomicAdd(dst + 3, acc.w);
}

// set MLP + c[g] = s[g] @ W1[128:256] + b1 (exact fp32)
__global__ void set_mlp_c_kernel(const float* __restrict__ uset,
                                 const float* __restrict__ Ws1,
                                 const float* __restrict__ bs1,
                                 const float* __restrict__ Ws2,
                                 const float* __restrict__ bs2,
                                 const float* __restrict__ W1g,
                                 const float* __restrict__ b1g,
                                 float* __restrict__ s_out) {
    __shared__ float x[8][256];
    __shared__ float h1[8][128];
    __shared__ float sres[8][128];
    const int j = threadIdx.x;
    const int rbase = blockIdx.x * 8;
    for (int idx = j; idx < 8 * 256; idx += 128) {
        int r = idx >> 8, k = idx & 255;
        x[r][k] = (k < 128) ? g_agg[(rbase + r) * H + k]
                            : uset[(size_t)(rbase + r) * H + (k - 128)];
    }
    __syncthreads();
    float acc[8];
    float b1 = bs1[j];
    #pragma unroll
    for (int r = 0; r < 8; ++r) acc[r] = b1;
    for (int k = 0; k < 256; ++k) {
        float w = Ws1[k * H + j];
        #pragma unroll
        for (int r = 0; r < 8; ++r) acc[r] += x[r][k] * w;
    }
    #pragma unroll
    for (int r = 0; r < 8; ++r) h1[r][j] = fmaxf(acc[r], 0.0f);
    __syncthreads();
    float b2 = bs2[j];
    #pragma unroll
    for (int r = 0; r < 8; ++r) acc[r] = b2;
    for (int k = 0; k < 128; ++k) {
        float w = Ws2[k * H + j];
        #pragma unroll
        for (int r = 0; r < 8; ++r) acc[r] += h1[r][k] * w;
    }
    #pragma unroll
    for (int r = 0; r < 8; ++r) {
        float v = fmaxf(acc[r], 0.0f);
        sres[r][j] = v;
        s_out[(size_t)(rbase + r) * H + j] = v;
    }
    __syncthreads();
    float bb = b1g[j];
    #pragma unroll
    for (int r = 0; r < 8; ++r) acc[r] = bb;
    for (int k = 0; k < 128; ++k) {
        float w = W1g[(size_t)(128 + k) * H + j];
        #pragma unroll
        for (int r = 0; r < 8; ++r) acc[r] += sres[r][k] * w;
    }
    #pragma unroll
    for (int r = 0; r < 8; ++r) g_c[(size_t)(rbase + r) * H + j] = acc[r];
}

// ============================================================================
// Fused node MLP: all-fp16 MMA, X streamed as fp16 via cp.async (dbl-buffered),
// c[seg] prefetched one tile ahead into registers.
// fp16 smem layout: 256B/row, o = row*256 + (((k>>3)^(row&7))<<4) + (k&7)*2.
// ============================================================================
#define W1_OFF   0        // 32768
#define W2_OFF   32768    // 32768
#define X0_OFF   65536    // 32768
#define X1_OFF   98304    // 32768
#define H1_OFF   131072   // 32768
#define B2S_OFF  163840   // 512
#define F_SMEM   164352

__global__ void __launch_bounds__(512, 1)
fused_node_mlp(const int* __restrict__ seg,
               const float* __restrict__ W1g,
               const float* __restrict__ W2g,
               const float* __restrict__ b2g,
               float* __restrict__ n_out,
               int numTiles) {
    extern __shared__ __align__(16) char smem[];
    const uint32_t sb = smem_u32_of(smem);
    float* b2s = (float*)(smem + B2S_OFF);

    const int tid = threadIdx.x, lane = tid & 31, wid = tid >> 5;
    const int wr = wid & 3, wc = wid >> 2;
    const int gr = lane >> 2, tg = lane & 3;

    // cp.async mapping: 512 threads x 4 x 16B = 32KB
    const int xrow = tid >> 2, xc = tid & 3;
    const char* n16base = (const char*)g_n16;

    // one-time: W1a fp16, W2 fp16, bias
    for (int idx = tid; idx < 128 * 128; idx += 512) {
        int n = idx >> 7, k = idx & 127;
        uint32_t o = (uint32_t)n * 256u + ((((uint32_t)k >> 3) ^ (n & 7)) << 4)
                   + ((uint32_t)k & 7) * 2u;
        *(__half*)(smem + W1_OFF + o) = __float2half_rn(W1g[(size_t)k * H + n]);
        *(__half*)(smem + W2_OFF + o) = __float2half_rn(W2g[(size_t)k * H + n]);
    }
    if (tid < 128) b2s[tid] = b2g[tid];

    // ldsm lane constants
    const int subA = lane & 7;
    const int arow0 = wr * 32 + ((lane >> 3) & 1) * 8 + subA;  // + mt*16
    const int hA = lane >> 4;
    const int subB = lane & 7;
    const int brow0 = wc * 32 + ((lane >> 4) & 1) * 8 + subB;  // + p*16
    const int hB = (lane >> 3) & 1;

    float acc[2][4][4];
    float2 cpre[2][2][4];
    int sga[2][2];

    // prologue: cp.async X(tile0) -> X0; seg+c prefetch for tile0
    {
        const int base = blockIdx.x * 128;
        #pragma unroll
        for (int i = 0; i < 4; ++i) {
            const uint32_t u = (uint32_t)(xc + i * 4);
            CP_ASYNC16(sb + X0_OFF + (uint32_t)xrow * 256u
                           + ((u ^ ((uint32_t)xrow & 7)) << 4),
                       n16base + (size_t)(base + xrow) * 256 + u * 16);
        }
        CP_COMMIT();
        #pragma unroll
        for (int mt = 0; mt < 2; ++mt) {
            const int ra = base + wr * 32 + mt * 16 + gr;
            sga[mt][0] = seg[ra];
            sga[mt][1] = seg[ra + 8];
        }
        #pragma unroll
        for (int mt = 0; mt < 2; ++mt)
            #pragma unroll
            for (int nt = 0; nt < 4; ++nt) {
                const int col = wc * 32 + nt * 8 + 2 * tg;
                cpre[mt][0][nt] = *(const float2*)&g_c[(size_t)sga[mt][0] * H + col];
                cpre[mt][1][nt] = *(const float2*)&g_c[(size_t)sga[mt][1] * H + col];
            }
    }

    uint32_t xcur = X0_OFF, xnxt = X1_OFF;

    for (int tile = blockIdx.x; tile < numTiles; tile += gridDim.x) {
        const int base = tile * 128;
        const int nxt = tile + gridDim.x;

        CP_WAIT(0);
        __syncthreads();   // (a) X[cur] visible; prev-tile h1 reads done

        // issue cp.async for next tile into xnxt (free: its layer1 reads done)
        if (nxt < numTiles) {
            const int nb = nxt * 128;
            #pragma unroll
            for (int i = 0; i < 4; ++i) {
                const uint32_t u = (uint32_t)(xc + i * 4);
                CP_ASYNC16(sb + xnxt + (uint32_t)xrow * 256u
                               + ((u ^ ((uint32_t)xrow & 7)) << 4),
                           n16base + (size_t)(nb + xrow) * 256 + u * 16);
            }
        }
        CP_COMMIT();

        // acc init = c[seg] (prefetched)
        #pragma unroll
        for (int mt = 0; mt < 2; ++mt)
            #pragma unroll
            for (int nt = 0; nt < 4; ++nt) {
                acc[mt][nt][0] = cpre[mt][0][nt].x;
                acc[mt][nt][1] = cpre[mt][0][nt].y;
                acc[mt][nt][2] = cpre[mt][1][nt].x;
                acc[mt][nt][3] = cpre[mt][1][nt].y;
            }

        // seg prefetch for next tile (independent LDG, hidden under layer1)
        if (nxt < numTiles) {
            const int nb = nxt * 128;
            #pragma unroll
            for (int mt = 0; mt < 2; ++mt) {
                const int ra = nb + wr * 32 + mt * 16 + gr;
                sga[mt][0] = seg[ra];
                sga[mt][1] = seg[ra + 8];
            }
        }

        // ---- layer1 (fp16): X @ W1a ----
        #pragma unroll
        for (int ks = 0; ks < 8; ++ks) {
            uint32_t A[2][4], B[2][4];
            #pragma unroll
            for (int mt = 0; mt < 2; ++mt) {
                uint32_t ad = sb + xcur + (uint32_t)(arow0 + mt * 16) * 256u
                            + ((((ks << 1) + hA) ^ subA) << 4);
                ldsm4(A[mt][0], A[mt][1], A[mt][2], A[mt][3], ad);
            }
            #pragma unroll
            for (int p = 0; p < 2; ++p) {
                uint32_t bd = sb + W1_OFF + (uint32_t)(brow0 + p * 16) * 256u
                            + ((((ks << 1) + hB) ^ subB) << 4);
                ldsm4(B[p][0], B[p][1], B[p][2], B[p][3], bd);
            }
            #pragma unroll
            for (int mt = 0; mt < 2; ++mt) {
                mma16(acc[mt][0], A[mt], B[0][0], B[0][1]);
                mma16(acc[mt][1], A[mt], B[0][2], B[0][3]);
                mma16(acc[mt][2], A[mt], B[1][0], B[1][1]);
                mma16(acc[mt][3], A[mt], B[1][2], B[1][3]);
            }
        }

        // ---- epilogue1: relu, fp16 -> h1 ----
        #pragma unroll
        for (int mt = 0; mt < 2; ++mt) {
            const int ra = wr * 32 + mt * 16 + gr;
            #pragma unroll
            for (int nt = 0; nt < 4; ++nt) {
                const int col = wc * 32 + nt * 8 + 2 * tg;
                const uint32_t unit = (uint32_t)(col >> 3);
                uint32_t v01 = pack_f16x2(fmaxf(acc[mt][nt][0], 0.0f),
                                          fmaxf(acc[mt][nt][1], 0.0f));
                *(uint32_t*)(smem + H1_OFF + (uint32_t)ra * 256u
                             + ((unit ^ ((uint32_t)ra & 7)) << 4)
                             + ((uint32_t)col & 7) * 2u) = v01;
                uint32_t v23 = pack_f16x2(fmaxf(acc[mt][nt][2], 0.0f),
                                          fmaxf(acc[mt][nt][3], 0.0f));
                *(uint32_t*)(smem + H1_OFF + (uint32_t)(ra + 8) * 256u
                             + ((unit ^ (((uint32_t)ra + 8) & 7)) << 4)
                             + ((uint32_t)col & 7) * 2u) = v23;
                #pragma unroll
                for (int j = 0; j < 4; ++j) acc[mt][nt][j] = 0.0f;
            }
        }
        __syncthreads();   // (b) h1 visible

        // c[seg] prefetch for next tile (dependent on sga, hidden under layer2)
        if (nxt < numTiles) {
            #pragma unroll
            for (int mt = 0; mt < 2; ++mt)
                #pragma unroll
                for (int nt = 0; nt < 4; ++nt) {
                    const int col = wc * 32 + nt * 8 + 2 * tg;
                    cpre[mt][0][nt] = *(const float2*)&g_c[(size_t)sga[mt][0] * H + col];
                    cpre[mt][1][nt] = *(const float2*)&g_c[(size_t)sga[mt][1] * H + col];
                }
        }

        // ---- layer2 (fp16): h1 @ W2 ----
        #pragma unroll
        for (int ks = 0; ks < 8; ++ks) {
            uint32_t A[2][4], B[2][4];
            #pragma unroll
            for (int mt = 0; mt < 2; ++mt) {
                uint32_t ad = sb + H1_OFF + (uint32_t)(arow0 + mt * 16) * 256u
                            + ((((ks << 1) + hA) ^ subA) << 4);
                ldsm4(A[mt][0], A[mt][1], A[mt][2], A[mt][3], ad);
            }
            #pragma unroll
            for (int p = 0; p < 2; ++p) {
                uint32_t bd = sb + W2_OFF + (uint32_t)(brow0 + p * 16) * 256u
                            + ((((ks << 1) + hB) ^ subB) << 4);
                ldsm4(B[p][0], B[p][1], B[p][2], B[p][3], bd);
            }
            #pragma unroll
            for (int mt = 0; mt < 2; ++mt) {
                mma16(acc[mt][0], A[mt], B[0][0], B[0][1]);
                mma16(acc[mt][1], A[mt], B[0][2], B[0][3]);
                mma16(acc[mt][2], A[mt], B[1][0], B[1][1]);
                mma16(acc[mt][3], A[mt], B[1][2], B[1][3]);
            }
        }

        // ---- epilogue2: +b2, relu, STG ----
        #pragma unroll
        for (int mt = 0; mt < 2; ++mt) {
            const int ra = base + wr * 32 + mt * 16 + gr;
            #pragma unroll
            for (int nt = 0; nt < 4; ++nt) {
                const int col = wc * 32 + nt * 8 + 2 * tg;
                const float bx = b2s[col], by = b2s[col + 1];
                float2 v;
                v.x = fmaxf(acc[mt][nt][0] + bx, 0.0f);
                v.y = fmaxf(acc[mt][nt][1] + by, 0.0f);
                *(float2*)&n_out[(size_t)ra * H + col] = v;
                v.x = fmaxf(acc[mt][nt][2] + bx, 0.0f);
                v.y = fmaxf(acc[mt][nt][3] + by, 0.0f);
                *(float2*)&n_out[(size_t)(ra + 8) * H + col] = v;
            }
        }

        uint32_t t = xcur; xcur = xnxt; xnxt = t;
    }
}

extern "C" void kernel_launch(void* const* d_in, const int* in_sizes, int n_in,
                              void* d_out, int out_size) {
    const float* uset  = (const float*)d_in[0];   // [G, H]
    const float* unode = (const float*)d_in[1];   // [N, H]
    const int*   seg   = (const int*)d_in[2];     // [N]
    const float* Ws1   = (const float*)d_in[3];
    const float* bs1   = (const float*)d_in[4];
    const float* Ws2   = (const float*)d_in[5];
    const float* bs2   = (const float*)d_in[6];
    const float* Wn1   = (const float*)d_in[7];
    const float* bn1   = (const float*)d_in[8];
    const float* Wn2   = (const float*)d_in[9];
    const float* bn2   = (const float*)d_in[10];

    const int G = in_sizes[0] / H;
    const int N = in_sizes[1] / H;

    float* s_out = (float*)d_out;                  // [G, H]
    float* n_out = (float*)d_out + (size_t)G * H;  // [N, H]

    zero_agg_kernel<<<(G * H + 255) / 256, 256>>>(G * H);
    seg_sum_cvt_kernel<<<N / 512, 256>>>((const float4*)unode, seg);
    set_mlp_c_kernel<<<G / 8, 128>>>(uset, Ws1, bs1, Ws2, bs2, Wn1, bn1, s_out);

    static int smem_set = 0;
    if (!smem_set) {
        cudaFuncSetAttribute(fused_node_mlp,
                             cudaFuncAttributeMaxDynamicSharedMemorySize, F_SMEM);
        smem_set = 1;
    }
    const int numTiles = N / 128;
    const int grid = numTiles < 148 ? numTiles : 148;
    fused_node_mlp<<<grid, 512, F_SMEM>>>(seg, Wn1, Wn2, bn2, n_out, numTiles);
}